// round 1
// baseline (speedup 1.0000x reference)
#include <cuda_runtime.h>
#include <math.h>

#define DIMC 768
#define HEADS 12
#define HID 3072
#define BATCH 8
#define FRAMES 16
#define NTOK 196
#define BT (BATCH*FRAMES)        // 128
#define TOKENS (BT*NTOK)         // 25088
#define EDIM 64
#define M_JOINT (FRAMES*NTOK)    // 3136
#define QKVD (3*DIMC)            // 2304

// ---------------- scratch (static device globals; no allocation) -------------
__device__ float g_xn  [(size_t)TOKENS*DIMC];
__device__ float g_qkv [(size_t)TOKENS*QKVD];
__device__ float g_attn[(size_t)TOKENS*DIMC];
__device__ float g_x2  [(size_t)TOKENS*DIMC];
__device__ float g_hdn [(size_t)TOKENS*HID];
__device__ float g_hdn2[(size_t)TOKENS*HID];
__device__ float g_kv  [BATCH*HEADS*EDIM*EDIM];
__device__ float g_ksum[BATCH*HEADS*EDIM];

// ---------------- LayerNorm: one block per 768-wide row ---------------------
__global__ __launch_bounds__(256) void ln_kernel(
    const float* __restrict__ x, const float* __restrict__ w,
    const float* __restrict__ b, float* __restrict__ out)
{
    size_t base = (size_t)blockIdx.x * DIMC;
    int t = threadIdx.x;
    float v0 = x[base + t];
    float v1 = x[base + t + 256];
    float v2 = x[base + t + 512];

    __shared__ float red[8];
    __shared__ float s_mean, s_rstd;

    // sum
    float s = v0 + v1 + v2;
    #pragma unroll
    for (int o = 16; o; o >>= 1) s += __shfl_down_sync(0xffffffffu, s, o);
    if ((t & 31) == 0) red[t >> 5] = s;
    __syncthreads();
    if (t == 0) {
        float tot = 0.f;
        #pragma unroll
        for (int i = 0; i < 8; i++) tot += red[i];
        s_mean = tot * (1.0f / DIMC);
    }
    __syncthreads();
    float mu = s_mean;
    float d0 = v0 - mu, d1 = v1 - mu, d2 = v2 - mu;
    float sq = d0*d0 + d1*d1 + d2*d2;
    #pragma unroll
    for (int o = 16; o; o >>= 1) sq += __shfl_down_sync(0xffffffffu, sq, o);
    __syncthreads();
    if ((t & 31) == 0) red[t >> 5] = sq;
    __syncthreads();
    if (t == 0) {
        float tot = 0.f;
        #pragma unroll
        for (int i = 0; i < 8; i++) tot += red[i];
        s_rstd = rsqrtf(tot * (1.0f / DIMC) + 1e-5f);
    }
    __syncthreads();
    float rs = s_rstd;
    out[base + t]       = d0 * rs * w[t]       + b[t];
    out[base + t + 256] = d1 * rs * w[t + 256] + b[t + 256];
    out[base + t + 512] = d2 * rs * w[t + 512] + b[t + 512];
}

// ---------------- SGEMM: C[M,N] = A[M,K] @ B[N,K]^T (+bias)(+resid) ---------
// BM=BN=128, BK=8, 256 threads, 8x8 per-thread microtile.
__global__ __launch_bounds__(256) void sgemm128(
    const float* __restrict__ A, const float* __restrict__ B,
    const float* __restrict__ bias, const float* __restrict__ resid,
    float* __restrict__ C, int M, int N, int K)
{
    __shared__ float As[8][128];
    __shared__ float Bs[8][128];
    int t = threadIdx.x;
    int blockM = blockIdx.y * 128;
    int blockN = blockIdx.x * 128;
    int lrow = t >> 1;
    int lcg  = (t & 1) * 4;
    const float* Aptr = A + (size_t)(blockM + lrow) * K + lcg;
    const float* Bptr = B + (size_t)(blockN + lrow) * K + lcg;
    int tx = t & 15, ty = t >> 4;

    float acc[8][8];
    #pragma unroll
    for (int i = 0; i < 8; i++)
        #pragma unroll
        for (int j = 0; j < 8; j++) acc[i][j] = 0.f;

    for (int k0 = 0; k0 < K; k0 += 8) {
        float4 a = *(const float4*)(Aptr + k0);
        float4 b = *(const float4*)(Bptr + k0);
        As[lcg+0][lrow] = a.x; As[lcg+1][lrow] = a.y;
        As[lcg+2][lrow] = a.z; As[lcg+3][lrow] = a.w;
        Bs[lcg+0][lrow] = b.x; Bs[lcg+1][lrow] = b.y;
        Bs[lcg+2][lrow] = b.z; Bs[lcg+3][lrow] = b.w;
        __syncthreads();
        #pragma unroll
        for (int k = 0; k < 8; k++) {
            float ra[8], rb[8];
            #pragma unroll
            for (int i = 0; i < 8; i++) ra[i] = As[k][ty*8 + i];
            #pragma unroll
            for (int j = 0; j < 8; j++) rb[j] = Bs[k][tx*8 + j];
            #pragma unroll
            for (int i = 0; i < 8; i++)
                #pragma unroll
                for (int j = 0; j < 8; j++)
                    acc[i][j] = fmaf(ra[i], rb[j], acc[i][j]);
        }
        __syncthreads();
    }

    #pragma unroll
    for (int i = 0; i < 8; i++) {
        size_t row = (size_t)(blockM + ty*8 + i);
        size_t off = row * N + blockN + tx*8;
        #pragma unroll
        for (int j = 0; j < 8; j++) {
            float v = acc[i][j];
            if (bias)  v += bias[blockN + tx*8 + j];
            if (resid) v += resid[off + j];
            C[off + j] = v;
        }
    }
}

// ---------------- linear attention: kv = k_^T v, ksum = sum k_ --------------
// one block per (b,h): 64x64 output, 256 threads each own a 4x4 tile
__global__ __launch_bounds__(256) void kv_kernel(
    const float* __restrict__ qkv, float* __restrict__ kv,
    float* __restrict__ ksum)
{
    __shared__ float Ks[32][64];
    __shared__ float Vs[32][64];
    int bh = blockIdx.x;
    int b = bh / HEADS, h = bh % HEADS;
    int t = threadIdx.x;
    int lrow = t >> 3;        // 0..31
    int lcol = (t & 7) * 8;   // 0..56
    int ge = t >> 4;          // 0..15
    int gd = t & 15;          // 0..15

    float acc[4][4];
    float ks[4];
    #pragma unroll
    for (int i = 0; i < 4; i++) { ks[i] = 0.f;
        #pragma unroll
        for (int j = 0; j < 4; j++) acc[i][j] = 0.f; }

    for (int c = 0; c < M_JOINT; c += 32) {
        int m = c + lrow;
        size_t base = ((size_t)(b * M_JOINT + m)) * QKVD + h * EDIM + lcol;
        float4 k1 = *(const float4*)(qkv + base + DIMC);
        float4 k2 = *(const float4*)(qkv + base + DIMC + 4);
        float4 v1 = *(const float4*)(qkv + base + 2*DIMC);
        float4 v2 = *(const float4*)(qkv + base + 2*DIMC + 4);
        Ks[lrow][lcol+0] = fmaxf(k1.x,0.f)+0.125f;
        Ks[lrow][lcol+1] = fmaxf(k1.y,0.f)+0.125f;
        Ks[lrow][lcol+2] = fmaxf(k1.z,0.f)+0.125f;
        Ks[lrow][lcol+3] = fmaxf(k1.w,0.f)+0.125f;
        Ks[lrow][lcol+4] = fmaxf(k2.x,0.f)+0.125f;
        Ks[lrow][lcol+5] = fmaxf(k2.y,0.f)+0.125f;
        Ks[lrow][lcol+6] = fmaxf(k2.z,0.f)+0.125f;
        Ks[lrow][lcol+7] = fmaxf(k2.w,0.f)+0.125f;
        Vs[lrow][lcol+0] = v1.x; Vs[lrow][lcol+1] = v1.y;
        Vs[lrow][lcol+2] = v1.z; Vs[lrow][lcol+3] = v1.w;
        Vs[lrow][lcol+4] = v2.x; Vs[lrow][lcol+5] = v2.y;
        Vs[lrow][lcol+6] = v2.z; Vs[lrow][lcol+7] = v2.w;
        __syncthreads();
        #pragma unroll 8
        for (int mm = 0; mm < 32; mm++) {
            float kv4[4], vv4[4];
            #pragma unroll
            for (int i = 0; i < 4; i++) kv4[i] = Ks[mm][ge*4 + i];
            #pragma unroll
            for (int j = 0; j < 4; j++) vv4[j] = Vs[mm][gd*4 + j];
            #pragma unroll
            for (int i = 0; i < 4; i++)
                #pragma unroll
                for (int j = 0; j < 4; j++)
                    acc[i][j] = fmaf(kv4[i], vv4[j], acc[i][j]);
            if (gd == 0) {
                #pragma unroll
                for (int i = 0; i < 4; i++) ks[i] += kv4[i];
            }
        }
        __syncthreads();
    }
    #pragma unroll
    for (int i = 0; i < 4; i++)
        #pragma unroll
        for (int j = 0; j < 4; j++)
            kv[(size_t)bh*4096 + (ge*4+i)*64 + gd*4+j] = acc[i][j];
    if (gd == 0) {
        #pragma unroll
        for (int i = 0; i < 4; i++) ksum[bh*64 + ge*4+i] = ks[i];
    }
}

// ---------------- attention output: per (token,h) 64x64 matvec --------------
__global__ __launch_bounds__(64) void attnout_kernel(
    const float* __restrict__ qkv, const float* __restrict__ kv,
    const float* __restrict__ ksum, float* __restrict__ attn)
{
    int token = blockIdx.x;
    int h = blockIdx.y;
    int bt = token / NTOK;
    int b = bt / FRAMES;
    int bh = b * HEADS + h;
    int d = threadIdx.x;

    __shared__ float qs[64];
    __shared__ float part[2];

    size_t qbase = (size_t)token * QKVD + h * EDIM;
    float qv = fmaxf(qkv[qbase + d], 0.f) + 0.125f;
    qs[d] = qv;
    float val = qv * ksum[bh*64 + d];
    #pragma unroll
    for (int o = 16; o; o >>= 1) val += __shfl_down_sync(0xffffffffu, val, o);
    if ((d & 31) == 0) part[d >> 5] = val;
    __syncthreads();
    float inv = 1.0f / (part[0] + part[1] + 1e-6f);

    const float* kvp = kv + (size_t)bh*4096 + d;
    float acc = 0.f;
    #pragma unroll 16
    for (int e = 0; e < 64; e++) acc = fmaf(qs[e], kvp[e*64], acc);
    attn[(size_t)token * DIMC + h * EDIM + d] = acc * inv;
}

// ---------------- depthwise 3x3 conv + bias + exact GELU --------------------
__global__ __launch_bounds__(256) void dwconv_gelu_kernel(
    const float* __restrict__ hdn, const float* __restrict__ w,
    const float* __restrict__ bias, float* __restrict__ out)
{
    int blk = blockIdx.x;
    int bn = blk / NTOK;
    int p  = blk % NTOK;
    int hh = p / 14, ww = p % 14;
    size_t ibase = (size_t)bn * NTOK * HID;

    for (int c = threadIdx.x; c < HID; c += 256) {
        float acc = bias[c];
        #pragma unroll
        for (int dy = -1; dy <= 1; dy++) {
            int y = hh + dy;
            if (y < 0 || y >= 14) continue;
            #pragma unroll
            for (int dx = -1; dx <= 1; dx++) {
                int xx = ww + dx;
                if (xx < 0 || xx >= 14) continue;
                acc = fmaf(hdn[ibase + (size_t)(y*14 + xx)*HID + c],
                           w[c*9 + (dy+1)*3 + (dx+1)], acc);
            }
        }
        out[ibase + (size_t)p*HID + c] =
            0.5f * acc * (1.0f + erff(acc * 0.70710678118654752f));
    }
}

// ---------------- launch ----------------------------------------------------
extern "C" void kernel_launch(void* const* d_in, const int* in_sizes, int n_in,
                              void* d_out, int out_size)
{
    const float* x      = (const float*)d_in[0];
    const float* ln1_w  = (const float*)d_in[1];
    const float* ln1_b  = (const float*)d_in[2];
    const float* qkv_w  = (const float*)d_in[3];
    const float* proj_w = (const float*)d_in[4];
    const float* proj_b = (const float*)d_in[5];
    const float* ln2_w  = (const float*)d_in[6];
    const float* ln2_b  = (const float*)d_in[7];
    const float* fc1_w  = (const float*)d_in[8];
    const float* fc1_b  = (const float*)d_in[9];
    const float* dw_w   = (const float*)d_in[10];
    const float* dw_b   = (const float*)d_in[11];
    const float* fc2_w  = (const float*)d_in[12];
    const float* fc2_b  = (const float*)d_in[13];
    float* out = (float*)d_out;

    float *p_xn, *p_qkv, *p_attn, *p_x2, *p_hdn, *p_hdn2, *p_kv, *p_ksum;
    cudaGetSymbolAddress((void**)&p_xn,   g_xn);
    cudaGetSymbolAddress((void**)&p_qkv,  g_qkv);
    cudaGetSymbolAddress((void**)&p_attn, g_attn);
    cudaGetSymbolAddress((void**)&p_x2,   g_x2);
    cudaGetSymbolAddress((void**)&p_hdn,  g_hdn);
    cudaGetSymbolAddress((void**)&p_hdn2, g_hdn2);
    cudaGetSymbolAddress((void**)&p_kv,   g_kv);
    cudaGetSymbolAddress((void**)&p_ksum, g_ksum);

    // 1) LN1
    ln_kernel<<<TOKENS, 256>>>(x, ln1_w, ln1_b, p_xn);
    // 2) QKV GEMM: (25088,768) @ (2304,768)^T
    sgemm128<<<dim3(QKVD/128, TOKENS/128), 256>>>(p_xn, qkv_w, nullptr, nullptr,
                                                  p_qkv, TOKENS, QKVD, DIMC);
    // 3) kv + ksum per (b,h)
    kv_kernel<<<BATCH*HEADS, 256>>>(p_qkv, p_kv, p_ksum);
    // 4) attention output
    attnout_kernel<<<dim3(TOKENS, HEADS), 64>>>(p_qkv, p_kv, p_ksum, p_attn);
    // 5) proj GEMM + bias + residual(x) -> x2
    sgemm128<<<dim3(DIMC/128, TOKENS/128), 256>>>(p_attn, proj_w, proj_b, x,
                                                  p_x2, TOKENS, DIMC, DIMC);
    // 6) LN2 (reuse xn buffer)
    ln_kernel<<<TOKENS, 256>>>(p_x2, ln2_w, ln2_b, p_xn);
    // 7) fc1 GEMM + bias -> hdn
    sgemm128<<<dim3(HID/128, TOKENS/128), 256>>>(p_xn, fc1_w, fc1_b, nullptr,
                                                 p_hdn, TOKENS, HID, DIMC);
    // 8) depthwise conv + bias + GELU -> hdn2
    dwconv_gelu_kernel<<<BT*NTOK, 256>>>(p_hdn, dw_w, dw_b, p_hdn2);
    // 9) fc2 GEMM + bias + residual(x2) -> out
    sgemm128<<<dim3(DIMC/128, TOKENS/128), 256>>>(p_hdn2, fc2_w, fc2_b, p_x2,
                                                  out, TOKENS, DIMC, HID);
    (void)in_sizes; (void)n_in; (void)out_size;
}